// round 2
// baseline (speedup 1.0000x reference)
#include <cuda_runtime.h>
#include <cstdint>
#include <cstddef>

#define Bc 8
#define Nc 384
#define Dc 256
#define Hc 1024
#define MR (Bc*Nc)   // 3072

// Scratch (device globals — allocation-free per harness rules)
__device__ float g_hidden[(size_t)MR * Hc];   // relu(fc1(x))  3072x1024
__device__ float g_y[(size_t)MR * Dc];        // x_hat * w     3072x256
__device__ float g_sumw;

// ---------------------------------------------------------------- sum(w)
__global__ void sumw_kernel(const float* __restrict__ w) {
    __shared__ float sm[8];
    int t = threadIdx.x;                    // 256 threads == Dc
    float v = w[t];
    #pragma unroll
    for (int off = 16; off; off >>= 1) v += __shfl_xor_sync(0xffffffffu, v, off);
    if ((t & 31) == 0) sm[t >> 5] = v;
    __syncthreads();
    if (t == 0) {
        float s = 0.f;
        #pragma unroll
        for (int k = 0; k < 8; k++) s += sm[k];
        g_sumw = s;
    }
}

// ---------------------------------------------------------------- GEMM1: hidden = relu(x @ fc1_w^T + b1)
// M=3072, N=1024, K=256.  BM=128 BN=128 BK=16, 256 thr, 8x8/thread. grid (8,24)=192 blocks.
__global__ __launch_bounds__(256) void gemm1_kernel(
    const float* __restrict__ A,     // x [3072,256]
    const float* __restrict__ Bw,    // fc1_w [1024,256]
    const float* __restrict__ bias)  // fc1_b [1024]
{
    constexpr int BM = 128, BN = 128, BK = 16, K = Dc;
    __shared__ __align__(16) float As[BK][BM];
    __shared__ __align__(16) float Bs[BK][BN];

    const int tid = threadIdx.x;
    const int m0 = blockIdx.y * BM, n0 = blockIdx.x * BN;
    const int ty = tid >> 4, tx = tid & 15;
    const int rm = tid >> 2;               // 0..63
    const int kq = (tid & 3) << 2;         // 0,4,8,12

    const float* Ap0 = A  + (size_t)(m0 + rm) * K + kq;
    const float* Ap1 = Ap0 + (size_t)64 * K;
    const float* Bp0 = Bw + (size_t)(n0 + rm) * K + kq;
    const float* Bp1 = Bp0 + (size_t)64 * K;

    float4 pa0 = *(const float4*)Ap0;
    float4 pa1 = *(const float4*)Ap1;
    float4 pb0 = *(const float4*)Bp0;
    float4 pb1 = *(const float4*)Bp1;

    float acc[8][8];
    #pragma unroll
    for (int i = 0; i < 8; i++)
        #pragma unroll
        for (int j = 0; j < 8; j++) acc[i][j] = 0.f;

    constexpr int NT = K / BK;
    for (int kt = 0; kt < NT; ++kt) {
        As[kq+0][rm]    = pa0.x; As[kq+1][rm]    = pa0.y; As[kq+2][rm]    = pa0.z; As[kq+3][rm]    = pa0.w;
        As[kq+0][rm+64] = pa1.x; As[kq+1][rm+64] = pa1.y; As[kq+2][rm+64] = pa1.z; As[kq+3][rm+64] = pa1.w;
        Bs[kq+0][rm]    = pb0.x; Bs[kq+1][rm]    = pb0.y; Bs[kq+2][rm]    = pb0.z; Bs[kq+3][rm]    = pb0.w;
        Bs[kq+0][rm+64] = pb1.x; Bs[kq+1][rm+64] = pb1.y; Bs[kq+2][rm+64] = pb1.z; Bs[kq+3][rm+64] = pb1.w;
        __syncthreads();

        if (kt + 1 < NT) {
            pa0 = *(const float4*)(Ap0 + (kt + 1) * BK);
            pa1 = *(const float4*)(Ap1 + (kt + 1) * BK);
            pb0 = *(const float4*)(Bp0 + (kt + 1) * BK);
            pb1 = *(const float4*)(Bp1 + (kt + 1) * BK);
        }

        #pragma unroll
        for (int k = 0; k < BK; k++) {
            float a[8], b[8];
            *(float4*)&a[0] = *(const float4*)&As[k][ty * 8];
            *(float4*)&a[4] = *(const float4*)&As[k][ty * 8 + 4];
            *(float4*)&b[0] = *(const float4*)&Bs[k][tx * 8];
            *(float4*)&b[4] = *(const float4*)&Bs[k][tx * 8 + 4];
            #pragma unroll
            for (int i = 0; i < 8; i++)
                #pragma unroll
                for (int j = 0; j < 8; j++) acc[i][j] = fmaf(a[i], b[j], acc[i][j]);
        }
        __syncthreads();
    }

    float bb[8];
    *(float4*)&bb[0] = *(const float4*)&bias[n0 + tx * 8];
    *(float4*)&bb[4] = *(const float4*)&bias[n0 + tx * 8 + 4];

    #pragma unroll
    for (int i = 0; i < 8; i++) {
        const size_t m = (size_t)(m0 + ty * 8 + i);
        float4 o0, o1;
        o0.x = fmaxf(acc[i][0] + bb[0], 0.f);
        o0.y = fmaxf(acc[i][1] + bb[1], 0.f);
        o0.z = fmaxf(acc[i][2] + bb[2], 0.f);
        o0.w = fmaxf(acc[i][3] + bb[3], 0.f);
        o1.x = fmaxf(acc[i][4] + bb[4], 0.f);
        o1.y = fmaxf(acc[i][5] + bb[5], 0.f);
        o1.z = fmaxf(acc[i][6] + bb[6], 0.f);
        o1.w = fmaxf(acc[i][7] + bb[7], 0.f);
        *(float4*)&g_hidden[m * Hc + n0 + tx * 8]     = o0;
        *(float4*)&g_hidden[m * Hc + n0 + tx * 8 + 4] = o1;
    }
}

// ---------------------------------------------------------------- GEMM2: x_hat = hidden @ fc2_w^T + b2 ; y = x_hat*w
// M=3072, N=256, K=1024. BM=64 BN=64 BK=16, 256 thr, 4x4/thread. grid (4,48)=192 blocks.
__global__ __launch_bounds__(256) void gemm2_kernel(
    const float* __restrict__ Bw,    // fc2_w [256,1024]
    const float* __restrict__ bias,  // fc2_b [256]
    const float* __restrict__ w,     // learn_w [256]
    float* __restrict__ xhat)        // out x_hat region [3072,256]
{
    constexpr int BM = 64, BN = 64, BK = 16, K = Hc;
    __shared__ __align__(16) float As[BK][BM];
    __shared__ __align__(16) float Bs[BK][BN];

    const int tid = threadIdx.x;
    const int m0 = blockIdx.y * BM, n0 = blockIdx.x * BN;
    const int ty = tid >> 4, tx = tid & 15;
    const int rm = tid >> 2;
    const int kq = (tid & 3) << 2;

    const float* Ap = g_hidden + (size_t)(m0 + rm) * K + kq;
    const float* Bp = Bw       + (size_t)(n0 + rm) * K + kq;

    float4 pa = *(const float4*)Ap;
    float4 pb = *(const float4*)Bp;

    float acc[4][4];
    #pragma unroll
    for (int i = 0; i < 4; i++)
        #pragma unroll
        for (int j = 0; j < 4; j++) acc[i][j] = 0.f;

    constexpr int NT = K / BK;
    for (int kt = 0; kt < NT; ++kt) {
        As[kq+0][rm] = pa.x; As[kq+1][rm] = pa.y; As[kq+2][rm] = pa.z; As[kq+3][rm] = pa.w;
        Bs[kq+0][rm] = pb.x; Bs[kq+1][rm] = pb.y; Bs[kq+2][rm] = pb.z; Bs[kq+3][rm] = pb.w;
        __syncthreads();

        if (kt + 1 < NT) {
            pa = *(const float4*)(Ap + (kt + 1) * BK);
            pb = *(const float4*)(Bp + (kt + 1) * BK);
        }

        #pragma unroll
        for (int k = 0; k < BK; k++) {
            float a[4], b[4];
            *(float4*)&a[0] = *(const float4*)&As[k][ty * 4];
            *(float4*)&b[0] = *(const float4*)&Bs[k][tx * 4];
            #pragma unroll
            for (int i = 0; i < 4; i++)
                #pragma unroll
                for (int j = 0; j < 4; j++) acc[i][j] = fmaf(a[i], b[j], acc[i][j]);
        }
        __syncthreads();
    }

    float bb[4], ww[4];
    *(float4*)&bb[0] = *(const float4*)&bias[n0 + tx * 4];
    *(float4*)&ww[0] = *(const float4*)&w[n0 + tx * 4];

    #pragma unroll
    for (int i = 0; i < 4; i++) {
        const size_t m = (size_t)(m0 + ty * 4 + i);
        float4 o, yv;
        o.x = acc[i][0] + bb[0]; o.y = acc[i][1] + bb[1];
        o.z = acc[i][2] + bb[2]; o.w = acc[i][3] + bb[3];
        yv.x = o.x * ww[0]; yv.y = o.y * ww[1]; yv.z = o.z * ww[2]; yv.w = o.w * ww[3];
        *(float4*)&xhat[m * Dc + n0 + tx * 4] = o;
        *(float4*)&g_y [m * Dc + n0 + tx * 4] = yv;
    }
}

// ---------------------------------------------------------------- distance + masked softmax
// One block = 24 rows of one batch, full 384 cols. 256 thr (8 warps x 3 rows x 12 col-groups).
__device__ __forceinline__ void cp_async16(uint32_t dst, const void* src) {
    asm volatile("cp.async.cg.shared.global [%0], [%1], 16;\n" :: "r"(dst), "l"(src));
}

#define XJ_STR 36   // 32 floats of d + pad (16B aligned rows, conflict-free LDS.128)

__global__ __launch_bounds__(256) void dist_kernel(
    const float* __restrict__ adj,
    const int* __restrict__ box_num,     // int32! (jax silently downcasts int64)
    float* __restrict__ out)
{
    extern __shared__ __align__(16) float sm[];
    float* s_xi = sm;                  // [24][256]
    float* s_xj = sm + 24 * Dc;        // [2][384][XJ_STR]

    const int tid = threadIdx.x;
    const int b  = blockIdx.y;
    const int i0 = blockIdx.x * 24;
    const float* yb = g_y + (size_t)b * Nc * Dc;

    // Load xi tile [24][256] (plain layout)
    #pragma unroll
    for (int p = 0; p < 6; p++) {
        int q = tid + 256 * p;             // 0..1535
        int i = q >> 6, c4 = (q & 63) << 2;
        *(float4*)&s_xi[i * Dc + c4] = *(const float4*)&yb[(size_t)(i0 + i) * Dc + c4];
    }

    const uint32_t xj_addr = (uint32_t)__cvta_generic_to_shared(s_xj);

    // Prefetch d-chunk 0 of all 384 xj rows
    #pragma unroll
    for (int p = 0; p < 12; p++) {
        int id = tid + 256 * p;            // 0..3071
        int j = id >> 3, u = id & 7;
        cp_async16(xj_addr + (uint32_t)((j * XJ_STR + u * 4) << 2),
                   &yb[(size_t)j * Dc + u * 4]);
    }
    asm volatile("cp.async.commit_group;\n" ::: "memory");

    float acc[3][12];
    #pragma unroll
    for (int r = 0; r < 3; r++)
        #pragma unroll
        for (int g = 0; g < 12; g++) acc[r][g] = 0.f;

    const int lane = tid & 31, ty = tid >> 5;
    const int ib = ty * 3;

    for (int c = 0; c < 8; c++) {
        if (c < 7) {
            uint32_t base = xj_addr + (uint32_t)(((c + 1) & 1) * (Nc * XJ_STR * 4));
            #pragma unroll
            for (int p = 0; p < 12; p++) {
                int id = tid + 256 * p;
                int j = id >> 3, u = id & 7;
                cp_async16(base + (uint32_t)((j * XJ_STR + u * 4) << 2),
                           &yb[(size_t)j * Dc + (c + 1) * 32 + u * 4]);
            }
            asm volatile("cp.async.commit_group;\n" ::: "memory");
            asm volatile("cp.async.wait_group 1;\n" ::: "memory");
        } else {
            asm volatile("cp.async.wait_group 0;\n" ::: "memory");
        }
        __syncthreads();

        const float* xjc = s_xj + (c & 1) * (Nc * XJ_STR);
        #pragma unroll
        for (int d4 = 0; d4 < 8; d4++) {
            const int dof = c * 32 + d4 * 4;
            const float4 x0 = *(const float4*)&s_xi[(ib + 0) * Dc + dof];
            const float4 x1 = *(const float4*)&s_xi[(ib + 1) * Dc + dof];
            const float4 x2 = *(const float4*)&s_xi[(ib + 2) * Dc + dof];
            #pragma unroll
            for (int g = 0; g < 12; g++) {
                const float4 xv = *(const float4*)&xjc[(lane + 32 * g) * XJ_STR + d4 * 4];
                float a0 = acc[0][g], a1 = acc[1][g], a2 = acc[2][g];
                a0 += fabsf(x0.x - xv.x); a0 += fabsf(x0.y - xv.y);
                a0 += fabsf(x0.z - xv.z); a0 += fabsf(x0.w - xv.w);
                a1 += fabsf(x1.x - xv.x); a1 += fabsf(x1.y - xv.y);
                a1 += fabsf(x1.z - xv.z); a1 += fabsf(x1.w - xv.w);
                a2 += fabsf(x2.x - xv.x); a2 += fabsf(x2.y - xv.y);
                a2 += fabsf(x2.z - xv.z); a2 += fabsf(x2.w - xv.w);
                acc[0][g] = a0; acc[1][g] = a1; acc[2][g] = a2;
            }
        }
        __syncthreads();
    }

    // Epilogue: mask, leaky_relu, warp-local softmax, +1e-10
    const int bn = box_num[b];
    const float sumw = g_sumw;
    const float* adjb = adj + (size_t)b * Nc * Nc;
    float* outb = out + (size_t)b * Nc * Nc;

    #pragma unroll
    for (int r = 0; r < 3; r++) {
        const int i = i0 + ib + r;
        const bool vi = i < bn;
        float v[12];
        float mx = -3.4e38f;
        #pragma unroll
        for (int g = 0; g < 12; g++) {
            const int j = lane + 32 * g;
            float t = acc[r][g];
            if (!(vi && (j < bn))) t -= sumw;                // mask * sum(w)
            t = (t >= 0.f) ? t : 0.01f * t;                  // leaky_relu
            v[g] = t;
            mx = fmaxf(mx, t);
        }
        #pragma unroll
        for (int off = 16; off; off >>= 1) mx = fmaxf(mx, __shfl_xor_sync(0xffffffffu, mx, off));
        float s = 0.f;
        #pragma unroll
        for (int g = 0; g < 12; g++) {
            const int j = lane + 32 * g;
            const float e = adjb[(size_t)i * Nc + j] * __expf(v[g] - mx);
            v[g] = e; s += e;
        }
        #pragma unroll
        for (int off = 16; off; off >>= 1) s += __shfl_xor_sync(0xffffffffu, s, off);
        const float inv = 1.f / s;
        #pragma unroll
        for (int g = 0; g < 12; g++) {
            const int j = lane + 32 * g;
            outb[(size_t)i * Nc + j] = v[g] * inv + 1e-10f;
        }
    }
}

// ---------------------------------------------------------------- launch
extern "C" void kernel_launch(void* const* d_in, const int* in_sizes, int n_in,
                              void* d_out, int out_size)
{
    const float* x       = (const float*)d_in[0];
    const float* adj     = (const float*)d_in[1];
    const int*   box_num = (const int*)d_in[2];
    const float* fc1_w   = (const float*)d_in[3];
    const float* fc1_b   = (const float*)d_in[4];
    const float* fc2_w   = (const float*)d_in[5];
    const float* fc2_b   = (const float*)d_in[6];
    const float* learn_w = (const float*)d_in[7];

    float* soft = (float*)d_out;                        // [8,384,384]
    float* xhat = soft + (size_t)Bc * Nc * Nc;          // [8,384,256]

    sumw_kernel<<<1, 256>>>(learn_w);
    gemm1_kernel<<<dim3(Hc / 128, MR / 128), 256>>>(x, fc1_w, fc1_b);
    gemm2_kernel<<<dim3(Dc / 64, MR / 64), 256>>>(fc2_w, fc2_b, learn_w, xhat);

    const int shm = (24 * Dc + 2 * Nc * XJ_STR) * 4;    // 135168 B
    cudaFuncSetAttribute(dist_kernel, cudaFuncAttributeMaxDynamicSharedMemorySize, shm);
    dist_kernel<<<dim3(Nc / 24, Bc), 256, shm>>>(adj, box_num, soft);
}